// round 2
// baseline (speedup 1.0000x reference)
#include <cuda_runtime.h>
#include <stdint.h>

#define B_ 4
#define N_ 1024
#define D_ 64

// Scratch (device globals — no allocation allowed)
__device__ float g_hs[B_ * N_ * D_];
__device__ float g_hd[B_ * N_ * D_];
__device__ float g_L[B_ * N_ * N_];

// ---------------------------------------------------------------------------
// Kernel 1: h_src = f @ W1[:D], h_dst = f @ W1[D:] (+ b1 folded into h_dst)
// block = 256 threads = 4 rows x 64 dims
// ---------------------------------------------------------------------------
__global__ void proj_kernel(const float* __restrict__ f,
                            const float* __restrict__ W1,
                            const float* __restrict__ b1) {
    int r = threadIdx.x >> 6;
    int d = threadIdx.x & 63;
    int row = blockIdx.x * 4 + r;
    __shared__ float fs[4][64];
    fs[r][d] = f[row * 64 + d];
    __syncthreads();
    float hs = 0.f, hd = 0.f;
#pragma unroll
    for (int k = 0; k < 64; ++k) {
        float fv = fs[r][k];
        hs = fmaf(fv, W1[k * 64 + d], hs);
        hd = fmaf(fv, W1[(64 + k) * 64 + d], hd);
    }
    hd += b1[d];
    g_hs[row * 64 + d] = hs;
    g_hd[row * 64 + d] = hd;
}

// ---------------------------------------------------------------------------
// Kernel 2: L[b,i,j] = sum_d relu(hs[b,i,d] + hd[b,j,d]) * w2[d] + b2
// 64x64 tile per block, 256 threads (16x16), 4x4 micro-tile.
// Shared arrays stored TRANSPOSED [d][row] so micro-tile reads are float4
// across rows (conflict-free LDS.128).
// ---------------------------------------------------------------------------
__global__ void logits_kernel(const float* __restrict__ W2,
                              const float* __restrict__ b2) {
    __shared__ __align__(16) float shs[64][68];  // [d][row_i]
    __shared__ __align__(16) float shd[64][68];  // [d][row_j]
    __shared__ float sw2[64];
    int b = blockIdx.z, ib = blockIdx.y, jb = blockIdx.x;
    int tid = threadIdx.x;

    const float* hsbase = g_hs + (b * N_ + ib * 64) * 64;
    const float* hdbase = g_hd + (b * N_ + jb * 64) * 64;
    for (int t = tid; t < 64 * 64; t += 256) {
        int r = t >> 6, d = t & 63;
        shs[d][r] = hsbase[t];
        shd[d][r] = hdbase[t];
    }
    if (tid < 64) sw2[tid] = W2[tid];
    __syncthreads();

    float b2v = b2[0];
    int tx = tid & 15, ty = tid >> 4;
    int ri = ty * 4, rj = tx * 4;

    float acc[4][4];
#pragma unroll
    for (int r = 0; r < 4; ++r)
#pragma unroll
        for (int c = 0; c < 4; ++c) acc[r][c] = 0.f;

#pragma unroll 16
    for (int d = 0; d < 64; ++d) {
        float4 a  = *(const float4*)&shs[d][ri];
        float4 cc = *(const float4*)&shd[d][rj];
        float w = sw2[d];
        float av[4] = {a.x, a.y, a.z, a.w};
        float cv[4] = {cc.x, cc.y, cc.z, cc.w};
#pragma unroll
        for (int r = 0; r < 4; ++r)
#pragma unroll
            for (int c = 0; c < 4; ++c)
                acc[r][c] = fmaf(fmaxf(av[r] + cv[c], 0.f), w, acc[r][c]);
    }

    float* outbase = g_L + ((size_t)(b * N_ + ib * 64 + ri)) * N_ + jb * 64 + rj;
#pragma unroll
    for (int r = 0; r < 4; ++r) {
        float4 o = make_float4(acc[r][0] + b2v, acc[r][1] + b2v,
                               acc[r][2] + b2v, acc[r][3] + b2v);
        *(float4*)(outbase + r * N_) = o;
    }
}

// ---------------------------------------------------------------------------
// Threefry2x32, key = jax.random.key(42) -> (0, 42), 20 rounds.
// Partitionable mode (JAX default): per-element 64-bit counter (hi=0, lo=L),
// 32-bit output = o0 ^ o1.
// ---------------------------------------------------------------------------
__device__ __forceinline__ uint32_t threefry_xor(uint32_t x0, uint32_t x1) {
    const uint32_t ks0 = 0u, ks1 = 42u, ks2 = 0x1BD11BDAu ^ 0u ^ 42u;
    x0 += ks0; x1 += ks1;
#define TF_RND(r) { x0 += x1; x1 = __funnelshift_l(x1, x1, (r)); x1 ^= x0; }
    TF_RND(13) TF_RND(15) TF_RND(26) TF_RND(6)   x0 += ks1; x1 += ks2 + 1u;
    TF_RND(17) TF_RND(29) TF_RND(16) TF_RND(24)  x0 += ks2; x1 += ks0 + 2u;
    TF_RND(13) TF_RND(15) TF_RND(26) TF_RND(6)   x0 += ks0; x1 += ks1 + 3u;
    TF_RND(17) TF_RND(29) TF_RND(16) TF_RND(24)  x0 += ks1; x1 += ks2 + 4u;
    TF_RND(13) TF_RND(15) TF_RND(26) TF_RND(6)   x0 += ks2; x1 += ks0 + 5u;
#undef TF_RND
    return x0 ^ x1;
}

// JAX uniform(minval=tiny, maxval=1) then gumbel = -log(-log(u))
__device__ __forceinline__ float gumbel_bits(uint32_t bits) {
    float f = __uint_as_float((bits >> 9) | 0x3f800000u) - 1.0f;
    f = fmaxf(f, 1.17549435e-38f);
    return -logf(-logf(f));
}

// ---------------------------------------------------------------------------
// Kernel 3: symmetrize + gumbel-softmax hard sample + outputs.
// 32x32 output tile; transposed L tile staged via shared memory.
// out layout: [adj (B*N*N)] [edge_logits (B*N*N)]
// ---------------------------------------------------------------------------
__global__ void symgum_kernel(float* __restrict__ out) {
    int b = blockIdx.z;
    int ib = blockIdx.y, jb = blockIdx.x;
    int tid = threadIdx.x;
    __shared__ float tT[32][33];

    for (int t = tid; t < 1024; t += 256) {
        int r = t >> 5, c = t & 31;
        tT[r][c] = g_L[((size_t)(b * N_ + jb * 32 + r)) * N_ + ib * 32 + c];
    }
    __syncthreads();

    float* adj = out;
    float* lg  = out + (size_t)B_ * N_ * N_;

#pragma unroll
    for (int s = 0; s < 4; ++s) {
        int q = tid + 256 * s;
        int ti = q >> 5, tj = q & 31;
        int i = ib * 32 + ti, j = jb * 32 + tj;
        size_t idx = ((size_t)(b * N_ + i)) * N_ + j;

        float sv = 0.5f * (g_L[idx] + tT[tj][ti]);

        // flat index into (B,N,N,2): L0 = idx*2 (k=0), L1 = idx*2+1 (k=1)
        uint32_t L0 = ((uint32_t)idx) << 1;
        uint32_t b0 = threefry_xor(0u, L0);
        uint32_t b1 = threefry_xor(0u, L0 + 1u);

        float g0 = gumbel_bits(b0);
        float g1 = gumbel_bits(b1);

        float mask = (i == j) ? 0.f : 1.f;
        adj[idx] = ((sv + g0) >= g1) ? mask : 0.f;
        lg[idx]  = sv;
    }
}

// ---------------------------------------------------------------------------
extern "C" void kernel_launch(void* const* d_in, const int* in_sizes, int n_in,
                              void* d_out, int out_size) {
    const float* f  = (const float*)d_in[0];
    const float* W1 = (const float*)d_in[1];
    const float* b1 = (const float*)d_in[2];
    const float* W2 = (const float*)d_in[3];
    const float* b2 = (const float*)d_in[4];

    proj_kernel<<<(B_ * N_) / 4, 256>>>(f, W1, b1);
    logits_kernel<<<dim3(N_ / 64, N_ / 64, B_), 256>>>(W2, b2);
    symgum_kernel<<<dim3(N_ / 32, N_ / 32, B_), 256>>>((float*)d_out);
}